// round 1
// baseline (speedup 1.0000x reference)
#include <cuda_runtime.h>
#include <cstdint>
#include <cstddef>

// Problem constants (all compile-time)
#define BB 4
#define SS 4096
#define DD 1024
#define HH 16
#define HDIM 64
#define FF 256
#define MM (BB*SS)          // 16384
#define NBH (BB*HH)         // 64
#define KSPLIT 8
#define SCH (SS/KSPLIT)     // 512

// -------- scratch (static device allocations; allowed) --------
__device__ float g_q[(size_t)MM*DD];        // 64MB
__device__ float g_k[(size_t)MM*DD];
__device__ float g_v[(size_t)MM*DD];
__device__ float g_qp[(size_t)NBH*SS*FF];   // 256MB
__device__ float g_kp[(size_t)NBH*SS*FF];
__device__ float g_kvp[(size_t)KSPLIT*NBH*FF*HDIM]; // 32MB
__device__ float g_ksp[(size_t)KSPLIT*NBH*FF];
__device__ float g_kv[(size_t)NBH*FF*HDIM];
__device__ float g_ks[(size_t)NBH*FF];
__device__ float g_attn[(size_t)MM*DD];

// ============================================================
// Kernel 1/5: C[M,N] = A[M,K] @ B[N,K]^T + bias[N]
// 128x128 tile, BK=16, 256 threads, 8x8 per thread
// ============================================================
__global__ __launch_bounds__(256) void gemm_nt_bias(
    const float* __restrict__ A, const float* __restrict__ Bm,
    const float* __restrict__ bias, float* __restrict__ C,
    int Mdim, int Ndim, int Kdim)
{
    constexpr int BM = 128, BN = 128, BK = 16;
    __shared__ float As[BK][BM];
    __shared__ float Bs[BK][BN];
    int tid = threadIdx.x;
    int brow = blockIdx.y * BM, bcol = blockIdx.x * BN;
    int lr = tid >> 2;          // 0..63
    int lc = (tid & 3) * 4;     // 0,4,8,12
    int ty = tid >> 4, tx = tid & 15;
    float acc[8][8] = {};

    const float* Ab = A + (size_t)brow * Kdim;
    const float* Bb = Bm + (size_t)bcol * Kdim;

    for (int k0 = 0; k0 < Kdim; k0 += BK) {
        #pragma unroll
        for (int p = 0; p < 2; p++) {
            int r = lr + p * 64;
            float4 a = *(const float4*)(Ab + (size_t)r * Kdim + k0 + lc);
            As[lc+0][r] = a.x; As[lc+1][r] = a.y; As[lc+2][r] = a.z; As[lc+3][r] = a.w;
            float4 b = *(const float4*)(Bb + (size_t)r * Kdim + k0 + lc);
            Bs[lc+0][r] = b.x; Bs[lc+1][r] = b.y; Bs[lc+2][r] = b.z; Bs[lc+3][r] = b.w;
        }
        __syncthreads();
        #pragma unroll
        for (int kk = 0; kk < BK; kk++) {
            float ra[8], rb[8];
            *(float4*)&ra[0] = *(const float4*)&As[kk][ty*8];
            *(float4*)&ra[4] = *(const float4*)&As[kk][ty*8+4];
            *(float4*)&rb[0] = *(const float4*)&Bs[kk][tx*8];
            *(float4*)&rb[4] = *(const float4*)&Bs[kk][tx*8+4];
            #pragma unroll
            for (int i = 0; i < 8; i++)
                #pragma unroll
                for (int j = 0; j < 8; j++)
                    acc[i][j] += ra[i] * rb[j];
        }
        __syncthreads();
    }
    #pragma unroll
    for (int i = 0; i < 8; i++) {
        size_t row = (size_t)(brow + ty*8 + i);
        float* Cp = C + row * Ndim + bcol + tx*8;
        float4 o0, o1;
        o0.x = acc[i][0] + bias[bcol+tx*8+0];
        o0.y = acc[i][1] + bias[bcol+tx*8+1];
        o0.z = acc[i][2] + bias[bcol+tx*8+2];
        o0.w = acc[i][3] + bias[bcol+tx*8+3];
        o1.x = acc[i][4] + bias[bcol+tx*8+4];
        o1.y = acc[i][5] + bias[bcol+tx*8+5];
        o1.z = acc[i][6] + bias[bcol+tx*8+6];
        o1.w = acc[i][7] + bias[bcol+tx*8+7];
        *(float4*)Cp = o0;
        *(float4*)(Cp + 4) = o1;
    }
}

// ============================================================
// Kernel 2: feature map.  Out[bh][s][f] = softplus( sum_d Y[b*S+s][h*64+d] * rf[h][d][f] )
// grid: (F/128=2, S/128=32, 64)
// ============================================================
__device__ __forceinline__ float softplus_f(float x) {
    return (x > 15.f) ? x : log1pf(expf(x));
}

__global__ __launch_bounds__(256) void feat_kernel(
    const float* __restrict__ Yin, const float* __restrict__ rf,
    float* __restrict__ Out)
{
    constexpr int BM = 128, BN = 128, BK = 16, K = HDIM;
    int bh = blockIdx.z;
    int b = bh >> 4, h = bh & 15;
    const float* Ab = Yin + ((size_t)b * SS) * DD + h * HDIM;
    const float* Bb = rf + (size_t)h * HDIM * FF;
    int brow = blockIdx.y * BM, bcol = blockIdx.x * BN;

    __shared__ float As[BK][BM];
    __shared__ float Bs[BK][BN];
    int tid = threadIdx.x;
    int ty = tid >> 4, tx = tid & 15;
    int lr = tid >> 2, lc = (tid & 3) * 4;
    float acc[8][8] = {};

    for (int k0 = 0; k0 < K; k0 += BK) {
        #pragma unroll
        for (int p = 0; p < 2; p++) {
            int r = lr + p * 64;
            float4 a = *(const float4*)(Ab + (size_t)(brow + r) * DD + k0 + lc);
            As[lc+0][r] = a.x; As[lc+1][r] = a.y; As[lc+2][r] = a.z; As[lc+3][r] = a.w;
        }
        {
            int r = tid >> 4;          // 0..15
            int c = (tid & 15) * 4;    // 0..60
            #pragma unroll
            for (int p = 0; p < 2; p++) {
                *(float4*)&Bs[r][c + p*64] =
                    *(const float4*)(Bb + (size_t)(k0 + r) * FF + bcol + c + p*64);
            }
        }
        __syncthreads();
        #pragma unroll
        for (int kk = 0; kk < BK; kk++) {
            float ra[8], rb[8];
            *(float4*)&ra[0] = *(const float4*)&As[kk][ty*8];
            *(float4*)&ra[4] = *(const float4*)&As[kk][ty*8+4];
            *(float4*)&rb[0] = *(const float4*)&Bs[kk][tx*8];
            *(float4*)&rb[4] = *(const float4*)&Bs[kk][tx*8+4];
            #pragma unroll
            for (int i = 0; i < 8; i++)
                #pragma unroll
                for (int j = 0; j < 8; j++)
                    acc[i][j] += ra[i] * rb[j];
        }
        __syncthreads();
    }
    #pragma unroll
    for (int i = 0; i < 8; i++) {
        size_t row = (size_t)bh * SS + brow + ty*8 + i;
        float* Op = Out + row * FF + bcol + tx*8;
        float4 o0, o1;
        o0.x = softplus_f(acc[i][0]); o0.y = softplus_f(acc[i][1]);
        o0.z = softplus_f(acc[i][2]); o0.w = softplus_f(acc[i][3]);
        o1.x = softplus_f(acc[i][4]); o1.y = softplus_f(acc[i][5]);
        o1.z = softplus_f(acc[i][6]); o1.w = softplus_f(acc[i][7]);
        *(float4*)Op = o0;
        *(float4*)(Op + 4) = o1;
    }
}

// ============================================================
// Kernel 3: kv partials per (bh, kc):
//   KVp[kc][bh][f][d] = sum_{s in chunk} kp[bh][s][f] * v[b*S+s][h*64+d]
//   KSp[kc][bh][f]    = sum_{s in chunk} kp[bh][s][f]
// one block per (bh, kc), 256 threads, output 256x64
// ============================================================
__global__ __launch_bounds__(256) void kv_kernel(
    const float* __restrict__ Kp, const float* __restrict__ Vm,
    float* __restrict__ KVp, float* __restrict__ KSp)
{
    int bh = blockIdx.x;
    int kc = blockIdx.y;
    int b = bh >> 4, h = bh & 15;
    const float* Ab = Kp + ((size_t)bh * SS + (size_t)kc * SCH) * FF;
    const float* Vb = Vm + ((size_t)(b * SS + kc * SCH)) * DD + h * HDIM;

    __shared__ float At[32][FF];     // 32KB
    __shared__ float Vt[32][HDIM];   // 8KB
    int tid = threadIdx.x;
    int ty = tid >> 3, tx = tid & 7;  // ty: 32 f-groups of 8; tx: 8 d-groups of 8
    float acc[8][8] = {};
    float rsum[8] = {};

    for (int s0 = 0; s0 < SCH; s0 += 32) {
        #pragma unroll
        for (int p = 0; p < 8; p++) {
            int idx = tid + p * 256;
            int r = idx >> 6, c = (idx & 63) * 4;
            *(float4*)&At[r][c] = *(const float4*)(Ab + (size_t)(s0 + r) * FF + c);
        }
        #pragma unroll
        for (int p = 0; p < 2; p++) {
            int idx = tid + p * 256;
            int r = idx >> 4, c = (idx & 15) * 4;
            *(float4*)&Vt[r][c] = *(const float4*)(Vb + (size_t)(s0 + r) * DD + c);
        }
        __syncthreads();
        #pragma unroll
        for (int ss = 0; ss < 32; ss++) {
            float ra[8], rb[8];
            *(float4*)&ra[0] = *(const float4*)&At[ss][ty*8];
            *(float4*)&ra[4] = *(const float4*)&At[ss][ty*8+4];
            *(float4*)&rb[0] = *(const float4*)&Vt[ss][tx*8];
            *(float4*)&rb[4] = *(const float4*)&Vt[ss][tx*8+4];
            #pragma unroll
            for (int i = 0; i < 8; i++) {
                rsum[i] += ra[i];
                #pragma unroll
                for (int j = 0; j < 8; j++)
                    acc[i][j] += ra[i] * rb[j];
            }
        }
        __syncthreads();
    }
    float* kvout = KVp + ((size_t)kc * NBH + bh) * (FF * HDIM);
    #pragma unroll
    for (int i = 0; i < 8; i++) {
        float* p = kvout + (size_t)(ty*8 + i) * HDIM + tx*8;
        *(float4*)p       = make_float4(acc[i][0], acc[i][1], acc[i][2], acc[i][3]);
        *(float4*)(p + 4) = make_float4(acc[i][4], acc[i][5], acc[i][6], acc[i][7]);
    }
    if (tx == 0) {
        float* kso = KSp + ((size_t)kc * NBH + bh) * FF;
        #pragma unroll
        for (int i = 0; i < 8; i++) kso[ty*8 + i] = rsum[i];
    }
}

// reduce split-K partials (deterministic, no atomics)
__global__ void reduce_kv(const float* __restrict__ KVp, const float* __restrict__ KSp,
                          float* __restrict__ KV, float* __restrict__ KS)
{
    const int NKV = NBH * FF * HDIM;   // 1,048,576
    const int NKS = NBH * FF;          // 16,384
    int i = blockIdx.x * blockDim.x + threadIdx.x;
    if (i < NKV) {
        float s = 0.f;
        #pragma unroll
        for (int kc = 0; kc < KSPLIT; kc++) s += KVp[(size_t)kc * NKV + i];
        KV[i] = s;
    }
    if (i < NKS) {
        float s = 0.f;
        #pragma unroll
        for (int kc = 0; kc < KSPLIT; kc++) s += KSp[(size_t)kc * NKS + i];
        KS[i] = s;
    }
}

// ============================================================
// Kernel 4: qkv + denom + divide; writes attn buffer [16384,1024]
//   attn[b*S+s][h*64+d] = (sum_f qp[bh][s][f]*kv[bh][f][d]) / (sum_f qp[bh][s][f]*ks[bh][f] + 1e-8)
// grid: (S/128=32, 64), block 256: ty 0..31 -> 4 s-rows each, tx 0..7 -> 8 d-cols each
// ============================================================
__global__ __launch_bounds__(256) void qkv_kernel(
    const float* __restrict__ Qp, const float* __restrict__ KV,
    const float* __restrict__ KS, float* __restrict__ Attn)
{
    constexpr int BM = 128, BK = 32;
    int bh = blockIdx.y;
    int b = bh >> 4, h = bh & 15;
    int brow = blockIdx.x * BM;
    const float* Ab  = Qp + ((size_t)bh * SS + brow) * FF;
    const float* KVb = KV + (size_t)bh * FF * HDIM;
    const float* KSb = KS + (size_t)bh * FF;

    __shared__ float At[BK][BM];     // 16KB (transposed: At[f][s])
    __shared__ float Bt[BK][HDIM];   // 8KB
    __shared__ float ks[BK];
    int tid = threadIdx.x;
    int ty = tid >> 3, tx = tid & 7;
    float acc[4][8] = {};
    float dacc[4] = {};

    for (int f0 = 0; f0 < FF; f0 += BK) {
        #pragma unroll
        for (int p = 0; p < 4; p++) {
            int idx = tid + p * 256;       // 0..1023
            int r = idx >> 3;              // s row 0..127
            int c = (idx & 7) * 4;         // f col 0..28
            float4 a = *(const float4*)(Ab + (size_t)r * FF + f0 + c);
            At[c+0][r] = a.x; At[c+1][r] = a.y; At[c+2][r] = a.z; At[c+3][r] = a.w;
        }
        #pragma unroll
        for (int p = 0; p < 2; p++) {
            int idx = tid + p * 256;
            int r = idx >> 4, c = (idx & 15) * 4;
            *(float4*)&Bt[r][c] = *(const float4*)(KVb + (size_t)(f0 + r) * HDIM + c);
        }
        if (tid < BK) ks[tid] = KSb[f0 + tid];
        __syncthreads();
        #pragma unroll
        for (int ff = 0; ff < BK; ff++) {
            float ra[4], rb[8];
            *(float4*)&ra[0] = *(const float4*)&At[ff][ty*4];
            *(float4*)&rb[0] = *(const float4*)&Bt[ff][tx*8];
            *(float4*)&rb[4] = *(const float4*)&Bt[ff][tx*8+4];
            float kv_s = ks[ff];
            #pragma unroll
            for (int i = 0; i < 4; i++) {
                dacc[i] += ra[i] * kv_s;
                #pragma unroll
                for (int j = 0; j < 8; j++)
                    acc[i][j] += ra[i] * rb[j];
            }
        }
        __syncthreads();
    }
    #pragma unroll
    for (int i = 0; i < 4; i++) {
        float inv = 1.f / (dacc[i] + 1e-8f);
        size_t row = (size_t)(b * SS + brow + ty*4 + i);
        float* p = Attn + row * DD + h * HDIM + tx*8;
        *(float4*)p = make_float4(acc[i][0]*inv, acc[i][1]*inv, acc[i][2]*inv, acc[i][3]*inv);
        *(float4*)(p+4) = make_float4(acc[i][4]*inv, acc[i][5]*inv, acc[i][6]*inv, acc[i][7]*inv);
    }
}

// ============================================================
extern "C" void kernel_launch(void* const* d_in, const int* in_sizes, int n_in,
                              void* d_out, int out_size)
{
    const float* x  = (const float*)d_in[0];
    const float* Wq = (const float*)d_in[1];
    const float* bq = (const float*)d_in[2];
    const float* Wk = (const float*)d_in[3];
    const float* bk = (const float*)d_in[4];
    const float* Wv = (const float*)d_in[5];
    const float* bv = (const float*)d_in[6];
    const float* Wo = (const float*)d_in[7];
    const float* bo = (const float*)d_in[8];
    const float* rf = (const float*)d_in[9];
    float* out = (float*)d_out;

    void *pq, *pk, *pv, *pqp, *pkp, *pkvp, *pksp, *pkv, *pks, *pattn;
    cudaGetSymbolAddress(&pq, g_q);
    cudaGetSymbolAddress(&pk, g_k);
    cudaGetSymbolAddress(&pv, g_v);
    cudaGetSymbolAddress(&pqp, g_qp);
    cudaGetSymbolAddress(&pkp, g_kp);
    cudaGetSymbolAddress(&pkvp, g_kvp);
    cudaGetSymbolAddress(&pksp, g_ksp);
    cudaGetSymbolAddress(&pkv, g_kv);
    cudaGetSymbolAddress(&pks, g_ks);
    cudaGetSymbolAddress(&pattn, g_attn);

    dim3 gProj(DD/128, MM/128);     // (8, 128)
    gemm_nt_bias<<<gProj, 256>>>(x, Wq, bq, (float*)pq, MM, DD, DD);
    gemm_nt_bias<<<gProj, 256>>>(x, Wk, bk, (float*)pk, MM, DD, DD);
    gemm_nt_bias<<<gProj, 256>>>(x, Wv, bv, (float*)pv, MM, DD, DD);

    dim3 gFeat(FF/128, SS/128, NBH); // (2, 32, 64)
    feat_kernel<<<gFeat, 256>>>((const float*)pq, rf, (float*)pqp);
    feat_kernel<<<gFeat, 256>>>((const float*)pk, rf, (float*)pkp);

    dim3 gKV(NBH, KSPLIT);           // (64, 8)
    kv_kernel<<<gKV, 256>>>((const float*)pkp, (const float*)pv,
                            (float*)pkvp, (float*)pksp);

    int nred = NBH * FF * HDIM;      // 1,048,576
    reduce_kv<<<(nred + 255)/256, 256>>>((const float*)pkvp, (const float*)pksp,
                                         (float*)pkv, (float*)pks);

    dim3 gQKV(SS/128, NBH);          // (32, 64)
    qkv_kernel<<<gQKV, 256>>>((const float*)pqp, (const float*)pkv,
                              (const float*)pks, (float*)pattn);

    gemm_nt_bias<<<gProj, 256>>>((const float*)pattn, Wo, bo, out, MM, DD, DD);
}

// round 2
// speedup vs baseline: 1.4050x; 1.4050x over previous
#include <cuda_runtime.h>
#include <mma.h>
#include <cstdint>
#include <cstddef>

using namespace nvcuda;

// Problem constants (all compile-time)
#define BB 4
#define SS 4096
#define DD 1024
#define HH 16
#define HDIM 64
#define FF 256
#define MM (BB*SS)          // 16384
#define NBH (BB*HH)         // 64
#define KSPLIT 8
#define SCH (SS/KSPLIT)     // 512

// -------- scratch (static device allocations; allowed) --------
__device__ float g_q[(size_t)MM*DD];        // 64MB
__device__ float g_k[(size_t)MM*DD];
__device__ float g_v[(size_t)MM*DD];
__device__ float g_qp[(size_t)NBH*SS*FF];   // 256MB
__device__ float g_kp[(size_t)NBH*SS*FF];
__device__ float g_kvp[(size_t)KSPLIT*NBH*FF*HDIM]; // 32MB
__device__ float g_ksp[(size_t)KSPLIT*NBH*FF];
__device__ float g_kv[(size_t)NBH*FF*HDIM];
__device__ float g_ks[(size_t)NBH*FF];
__device__ float g_attn[(size_t)MM*DD];

__device__ __forceinline__ float to_tf32(float x) {
    float r;
    asm("cvt.rna.tf32.f32 %0, %1;" : "=f"(r) : "f"(x));
    return r;
}

// ============================================================
// Kernel 1: C[M,N] = A[M,K] @ B[N,K]^T + bias[N]  -- tf32 tensor cores
// 128x128 tile, BK=32, 256 threads = 8 warps (2m x 4n), warp tile 64x32
// ============================================================
__global__ __launch_bounds__(256) void gemm_nt_bias_tc(
    const float* __restrict__ A, const float* __restrict__ Bm,
    const float* __restrict__ bias, float* __restrict__ C,
    int Ndim, int Kdim)
{
    constexpr int BM = 128, BN = 128, BK = 32, LD = 36;
    __shared__ float As[BM][LD];
    __shared__ float Bs[BN][LD];
    __shared__ float scratch[8][16][16];

    int tid = threadIdx.x, wid = tid >> 5, lane = tid & 31;
    int wm = wid >> 2, wn = wid & 3;
    int brow = blockIdx.y * BM, bcol = blockIdx.x * BN;

    wmma::fragment<wmma::matrix_a, 16, 16, 8, wmma::precision::tf32, wmma::row_major> fa[4];
    wmma::fragment<wmma::matrix_b, 16, 16, 8, wmma::precision::tf32, wmma::col_major> fb[2];
    wmma::fragment<wmma::accumulator, 16, 16, 8, float> facc[4][2];
    #pragma unroll
    for (int i = 0; i < 4; i++)
        #pragma unroll
        for (int j = 0; j < 2; j++)
            wmma::fill_fragment(facc[i][j], 0.0f);

    const float* Ab = A + (size_t)brow * Kdim;
    const float* Bb = Bm + (size_t)bcol * Kdim;
    int r = tid >> 1, cbase = (tid & 1) * 16;

    for (int k0 = 0; k0 < Kdim; k0 += BK) {
        #pragma unroll
        for (int q = 0; q < 4; q++) {
            float4 a = *(const float4*)(Ab + (size_t)r * Kdim + k0 + cbase + q * 4);
            As[r][cbase + q*4 + 0] = to_tf32(a.x);
            As[r][cbase + q*4 + 1] = to_tf32(a.y);
            As[r][cbase + q*4 + 2] = to_tf32(a.z);
            As[r][cbase + q*4 + 3] = to_tf32(a.w);
            float4 b = *(const float4*)(Bb + (size_t)r * Kdim + k0 + cbase + q * 4);
            Bs[r][cbase + q*4 + 0] = to_tf32(b.x);
            Bs[r][cbase + q*4 + 1] = to_tf32(b.y);
            Bs[r][cbase + q*4 + 2] = to_tf32(b.z);
            Bs[r][cbase + q*4 + 3] = to_tf32(b.w);
        }
        __syncthreads();
        #pragma unroll
        for (int kk = 0; kk < 4; kk++) {
            #pragma unroll
            for (int i = 0; i < 4; i++)
                wmma::load_matrix_sync(fa[i], &As[wm*64 + i*16][kk*8], LD);
            #pragma unroll
            for (int j = 0; j < 2; j++)
                wmma::load_matrix_sync(fb[j], &Bs[wn*32 + j*16][kk*8], LD);
            #pragma unroll
            for (int i = 0; i < 4; i++)
                #pragma unroll
                for (int j = 0; j < 2; j++)
                    wmma::mma_sync(facc[i][j], fa[i], fb[j], facc[i][j]);
        }
        __syncthreads();
    }

    // epilogue: per-warp 16x16 staging + bias
    int rr = lane >> 1, cc = (lane & 1) * 8;
    #pragma unroll
    for (int i = 0; i < 4; i++) {
        #pragma unroll
        for (int j = 0; j < 2; j++) {
            wmma::store_matrix_sync(&scratch[wid][0][0], facc[i][j], 16, wmma::mem_row_major);
            __syncwarp();
            int gr = brow + wm*64 + i*16 + rr;
            int gc = bcol + wn*32 + j*16 + cc;
            float4 o0, o1;
            o0.x = scratch[wid][rr][cc+0] + bias[gc+0];
            o0.y = scratch[wid][rr][cc+1] + bias[gc+1];
            o0.z = scratch[wid][rr][cc+2] + bias[gc+2];
            o0.w = scratch[wid][rr][cc+3] + bias[gc+3];
            o1.x = scratch[wid][rr][cc+4] + bias[gc+4];
            o1.y = scratch[wid][rr][cc+5] + bias[gc+5];
            o1.z = scratch[wid][rr][cc+6] + bias[gc+6];
            o1.w = scratch[wid][rr][cc+7] + bias[gc+7];
            *(float4*)(C + (size_t)gr * Ndim + gc) = o0;
            *(float4*)(C + (size_t)gr * Ndim + gc + 4) = o1;
            __syncwarp();
        }
    }
}

// ============================================================
// Kernel 2: feature map (tf32 tensor cores) + softplus
// Out[bh][s][f] = softplus( sum_d Y[b*S+s][h*64+d] * rf[h][d][f] )
// grid: (F/128=2, S/128=32, 64); NN GEMM, K=64
// ============================================================
__device__ __forceinline__ float softplus_f(float x) {
    return (x > 15.f) ? x : log1pf(expf(x));
}

__global__ __launch_bounds__(256) void feat_tc(
    const float* __restrict__ Yin, const float* __restrict__ rf,
    float* __restrict__ Out)
{
    constexpr int BM = 128, BK = 32, LDA = 36, LDB = 132;
    __shared__ float As[BM][LDA];      // [s][d]
    __shared__ float Bs[BK][LDB];      // [d][f]
    __shared__ float scratch[8][16][16];

    int bh = blockIdx.z;
    int b = bh >> 4, h = bh & 15;
    int brow = blockIdx.y * BM, bcol = blockIdx.x * 128;
    const float* Ab = Yin + ((size_t)b * SS) * DD + h * HDIM;
    const float* Bb = rf + (size_t)h * HDIM * FF;

    int tid = threadIdx.x, wid = tid >> 5, lane = tid & 31;
    int wm = wid >> 2, wn = wid & 3;

    wmma::fragment<wmma::matrix_a, 16, 16, 8, wmma::precision::tf32, wmma::row_major> fa[4];
    wmma::fragment<wmma::matrix_b, 16, 16, 8, wmma::precision::tf32, wmma::row_major> fb[2];
    wmma::fragment<wmma::accumulator, 16, 16, 8, float> facc[4][2];
    #pragma unroll
    for (int i = 0; i < 4; i++)
        #pragma unroll
        for (int j = 0; j < 2; j++)
            wmma::fill_fragment(facc[i][j], 0.0f);

    int ra = tid >> 1, ca = (tid & 1) * 16;
    int rb = tid >> 3, cb = (tid & 7) * 16;

    #pragma unroll
    for (int k0 = 0; k0 < HDIM; k0 += BK) {
        #pragma unroll
        for (int q = 0; q < 4; q++) {
            float4 a = *(const float4*)(Ab + (size_t)(brow + ra) * DD + k0 + ca + q * 4);
            As[ra][ca + q*4 + 0] = to_tf32(a.x);
            As[ra][ca + q*4 + 1] = to_tf32(a.y);
            As[ra][ca + q*4 + 2] = to_tf32(a.z);
            As[ra][ca + q*4 + 3] = to_tf32(a.w);
            float4 bv = *(const float4*)(Bb + (size_t)(k0 + rb) * FF + bcol + cb + q * 4);
            Bs[rb][cb + q*4 + 0] = to_tf32(bv.x);
            Bs[rb][cb + q*4 + 1] = to_tf32(bv.y);
            Bs[rb][cb + q*4 + 2] = to_tf32(bv.z);
            Bs[rb][cb + q*4 + 3] = to_tf32(bv.w);
        }
        __syncthreads();
        #pragma unroll
        for (int kk = 0; kk < 4; kk++) {
            #pragma unroll
            for (int i = 0; i < 4; i++)
                wmma::load_matrix_sync(fa[i], &As[wm*64 + i*16][kk*8], LDA);
            #pragma unroll
            for (int j = 0; j < 2; j++)
                wmma::load_matrix_sync(fb[j], &Bs[kk*8][wn*32 + j*16], LDB);
            #pragma unroll
            for (int i = 0; i < 4; i++)
                #pragma unroll
                for (int j = 0; j < 2; j++)
                    wmma::mma_sync(facc[i][j], fa[i], fb[j], facc[i][j]);
        }
        __syncthreads();
    }

    int rr = lane >> 1, cc = (lane & 1) * 8;
    #pragma unroll
    for (int i = 0; i < 4; i++) {
        #pragma unroll
        for (int j = 0; j < 2; j++) {
            wmma::store_matrix_sync(&scratch[wid][0][0], facc[i][j], 16, wmma::mem_row_major);
            __syncwarp();
            size_t row = (size_t)bh * SS + brow + wm*64 + i*16 + rr;
            int col = bcol + wn*32 + j*16 + cc;
            float4 o0, o1;
            o0.x = softplus_f(scratch[wid][rr][cc+0]);
            o0.y = softplus_f(scratch[wid][rr][cc+1]);
            o0.z = softplus_f(scratch[wid][rr][cc+2]);
            o0.w = softplus_f(scratch[wid][rr][cc+3]);
            o1.x = softplus_f(scratch[wid][rr][cc+4]);
            o1.y = softplus_f(scratch[wid][rr][cc+5]);
            o1.z = softplus_f(scratch[wid][rr][cc+6]);
            o1.w = softplus_f(scratch[wid][rr][cc+7]);
            *(float4*)(Out + row * FF + col) = o0;
            *(float4*)(Out + row * FF + col + 4) = o1;
            __syncwarp();
        }
    }
}

// ============================================================
// Kernel 3: kv partials per (bh, kc)  (fp32, unchanged)
// ============================================================
__global__ __launch_bounds__(256) void kv_kernel(
    const float* __restrict__ Kp, const float* __restrict__ Vm,
    float* __restrict__ KVp, float* __restrict__ KSp)
{
    int bh = blockIdx.x;
    int kc = blockIdx.y;
    int b = bh >> 4, h = bh & 15;
    const float* Ab = Kp + ((size_t)bh * SS + (size_t)kc * SCH) * FF;
    const float* Vb = Vm + ((size_t)(b * SS + kc * SCH)) * DD + h * HDIM;

    __shared__ float At[32][FF];
    __shared__ float Vt[32][HDIM];
    int tid = threadIdx.x;
    int ty = tid >> 3, tx = tid & 7;
    float acc[8][8] = {};
    float rsum[8] = {};

    for (int s0 = 0; s0 < SCH; s0 += 32) {
        #pragma unroll
        for (int p = 0; p < 8; p++) {
            int idx = tid + p * 256;
            int r = idx >> 6, c = (idx & 63) * 4;
            *(float4*)&At[r][c] = *(const float4*)(Ab + (size_t)(s0 + r) * FF + c);
        }
        #pragma unroll
        for (int p = 0; p < 2; p++) {
            int idx = tid + p * 256;
            int r = idx >> 4, c = (idx & 15) * 4;
            *(float4*)&Vt[r][c] = *(const float4*)(Vb + (size_t)(s0 + r) * DD + c);
        }
        __syncthreads();
        #pragma unroll
        for (int ss = 0; ss < 32; ss++) {
            float ra[8], rb[8];
            *(float4*)&ra[0] = *(const float4*)&At[ss][ty*8];
            *(float4*)&ra[4] = *(const float4*)&At[ss][ty*8+4];
            *(float4*)&rb[0] = *(const float4*)&Vt[ss][tx*8];
            *(float4*)&rb[4] = *(const float4*)&Vt[ss][tx*8+4];
            #pragma unroll
            for (int i = 0; i < 8; i++) {
                rsum[i] += ra[i];
                #pragma unroll
                for (int j = 0; j < 8; j++)
                    acc[i][j] += ra[i] * rb[j];
            }
        }
        __syncthreads();
    }
    float* kvout = KVp + ((size_t)kc * NBH + bh) * (FF * HDIM);
    #pragma unroll
    for (int i = 0; i < 8; i++) {
        float* p = kvout + (size_t)(ty*8 + i) * HDIM + tx*8;
        *(float4*)p       = make_float4(acc[i][0], acc[i][1], acc[i][2], acc[i][3]);
        *(float4*)(p + 4) = make_float4(acc[i][4], acc[i][5], acc[i][6], acc[i][7]);
    }
    if (tx == 0) {
        float* kso = KSp + ((size_t)kc * NBH + bh) * FF;
        #pragma unroll
        for (int i = 0; i < 8; i++) kso[ty*8 + i] = rsum[i];
    }
}

__global__ void reduce_kv(const float* __restrict__ KVp, const float* __restrict__ KSp,
                          float* __restrict__ KV, float* __restrict__ KS)
{
    const int NKV = NBH * FF * HDIM;
    const int NKS = NBH * FF;
    int i = blockIdx.x * blockDim.x + threadIdx.x;
    if (i < NKV) {
        float s = 0.f;
        #pragma unroll
        for (int kc = 0; kc < KSPLIT; kc++) s += KVp[(size_t)kc * NKV + i];
        KV[i] = s;
    }
    if (i < NKS) {
        float s = 0.f;
        #pragma unroll
        for (int kc = 0; kc < KSPLIT; kc++) s += KSp[(size_t)kc * NKS + i];
        KS[i] = s;
    }
}

// ============================================================
// Kernel 4: qkv + denom + divide (fp32, unchanged)
// ============================================================
__global__ __launch_bounds__(256) void qkv_kernel(
    const float* __restrict__ Qp, const float* __restrict__ KV,
    const float* __restrict__ KS, float* __restrict__ Attn)
{
    constexpr int BM = 128, BK = 32;
    int bh = blockIdx.y;
    int b = bh >> 4, h = bh & 15;
    int brow = blockIdx.x * BM;
    const float* Ab  = Qp + ((size_t)bh * SS + brow) * FF;
    const float* KVb = KV + (size_t)bh * FF * HDIM;
    const float* KSb = KS + (size_t)bh * FF;

    __shared__ float At[BK][BM];
    __shared__ float Bt[BK][HDIM];
    __shared__ float ks[BK];
    int tid = threadIdx.x;
    int ty = tid >> 3, tx = tid & 7;
    float acc[4][8] = {};
    float dacc[4] = {};

    for (int f0 = 0; f0 < FF; f0 += BK) {
        #pragma unroll
        for (int p = 0; p < 4; p++) {
            int idx = tid + p * 256;
            int r = idx >> 3;
            int c = (idx & 7) * 4;
            float4 a = *(const float4*)(Ab + (size_t)r * FF + f0 + c);
            At[c+0][r] = a.x; At[c+1][r] = a.y; At[c+2][r] = a.z; At[c+3][r] = a.w;
        }
        #pragma unroll
        for (int p = 0; p < 2; p++) {
            int idx = tid + p * 256;
            int r = idx >> 4, c = (idx & 15) * 4;
            *(float4*)&Bt[r][c] = *(const float4*)(KVb + (size_t)(f0 + r) * HDIM + c);
        }
        if (tid < BK) ks[tid] = KSb[f0 + tid];
        __syncthreads();
        #pragma unroll
        for (int ff = 0; ff < BK; ff++) {
            float ra[4], rb[8];
            *(float4*)&ra[0] = *(const float4*)&At[ff][ty*4];
            *(float4*)&rb[0] = *(const float4*)&Bt[ff][tx*8];
            *(float4*)&rb[4] = *(const float4*)&Bt[ff][tx*8+4];
            float kv_s = ks[ff];
            #pragma unroll
            for (int i = 0; i < 4; i++) {
                dacc[i] += ra[i] * kv_s;
                #pragma unroll
                for (int j = 0; j < 8; j++)
                    acc[i][j] += ra[i] * rb[j];
            }
        }
        __syncthreads();
    }
    #pragma unroll
    for (int i = 0; i < 4; i++) {
        float inv = 1.f / (dacc[i] + 1e-8f);
        size_t row = (size_t)(b * SS + brow + ty*4 + i);
        float* p = Attn + row * DD + h * HDIM + tx*8;
        *(float4*)p = make_float4(acc[i][0]*inv, acc[i][1]*inv, acc[i][2]*inv, acc[i][3]*inv);
        *(float4*)(p+4) = make_float4(acc[i][4]*inv, acc[i][5]*inv, acc[i][6]*inv, acc[i][7]*inv);
    }
}

// ============================================================
extern "C" void kernel_launch(void* const* d_in, const int* in_sizes, int n_in,
                              void* d_out, int out_size)
{
    const float* x  = (const float*)d_in[0];
    const float* Wq = (const float*)d_in[1];
    const float* bq = (const float*)d_in[2];
    const float* Wk = (const float*)d_in[3];
    const float* bk = (const float*)d_in[4];
    const float* Wv = (const float*)d_in[5];
    const float* bv = (const float*)d_in[6];
    const float* Wo = (const float*)d_in[7];
    const float* bo = (const float*)d_in[8];
    const float* rf = (const float*)d_in[9];
    float* out = (float*)d_out;

    void *pq, *pk, *pv, *pqp, *pkp, *pkvp, *pksp, *pkv, *pks, *pattn;
    cudaGetSymbolAddress(&pq, g_q);
    cudaGetSymbolAddress(&pk, g_k);
    cudaGetSymbolAddress(&pv, g_v);
    cudaGetSymbolAddress(&pqp, g_qp);
    cudaGetSymbolAddress(&pkp, g_kp);
    cudaGetSymbolAddress(&pkvp, g_kvp);
    cudaGetSymbolAddress(&pksp, g_ksp);
    cudaGetSymbolAddress(&pkv, g_kv);
    cudaGetSymbolAddress(&pks, g_ks);
    cudaGetSymbolAddress(&pattn, g_attn);

    dim3 gProj(DD/128, MM/128);     // (8, 128)
    gemm_nt_bias_tc<<<gProj, 256>>>(x, Wq, bq, (float*)pq, DD, DD);
    gemm_nt_bias_tc<<<gProj, 256>>>(x, Wk, bk, (float*)pk, DD, DD);
    gemm_nt_bias_tc<<<gProj, 256>>>(x, Wv, bv, (float*)pv, DD, DD);

    dim3 gFeat(FF/128, SS/128, NBH); // (2, 32, 64)
    feat_tc<<<gFeat, 256>>>((const float*)pq, rf, (float*)pqp);
    feat_tc<<<gFeat, 256>>>((const float*)pk, rf, (float*)pkp);

    dim3 gKV(NBH, KSPLIT);           // (64, 8)
    kv_kernel<<<gKV, 256>>>((const float*)pkp, (const float*)pv,
                            (float*)pkvp, (float*)pksp);

    int nred = NBH * FF * HDIM;
    reduce_kv<<<(nred + 255)/256, 256>>>((const float*)pkvp, (const float*)pksp,
                                         (float*)pkv, (float*)pks);

    dim3 gQKV(SS/128, NBH);          // (32, 64)
    qkv_kernel<<<gQKV, 256>>>((const float*)pqp, (const float*)pkv,
                              (const float*)pks, (float*)pattn);

    gemm_nt_bias_tc<<<gProj, 256>>>((const float*)pattn, Wo, bo, out, DD, DD);
}

// round 5
// speedup vs baseline: 2.6214x; 1.8657x over previous
#include <cuda_runtime.h>
#include <cstdint>
#include <cstddef>

// Problem constants (all compile-time)
#define BB 4
#define SS 4096
#define DD 1024
#define HH 16
#define HDIM 64
#define FF 256
#define MM (BB*SS)          // 16384
#define NBH (BB*HH)         // 64
#define KSPLIT 8
#define SCH (SS/KSPLIT)     // 512

// -------- scratch (static device allocations; allowed) --------
__device__ float g_q[(size_t)MM*DD];
__device__ float g_k[(size_t)MM*DD];
__device__ float g_v[(size_t)MM*DD];
__device__ float g_qp[(size_t)NBH*SS*FF];
__device__ float g_kp[(size_t)NBH*SS*FF];
__device__ float g_kvp[(size_t)KSPLIT*NBH*FF*HDIM];
__device__ float g_ksp[(size_t)KSPLIT*NBH*FF];
__device__ float g_kv[(size_t)NBH*FF*HDIM];
__device__ float g_ks[(size_t)NBH*FF];
__device__ float g_attn[(size_t)MM*DD];
__device__ float g_xr[(size_t)MM*DD];
__device__ float g_wqr[(size_t)DD*DD];
__device__ float g_wkr[(size_t)DD*DD];
__device__ float g_wvr[(size_t)DD*DD];
__device__ float g_wor[(size_t)DD*DD];

__device__ __forceinline__ float to_tf32(float x) {
    float r;
    asm("cvt.rna.tf32.f32 %0, %1;" : "=f"(r) : "f"(x));
    return r;
}

__device__ __forceinline__ uint32_t smem_u32(const void* p) {
    uint32_t a;
    asm("{ .reg .u64 t; cvta.to.shared.u64 t, %1; cvt.u32.u64 %0, t; }" : "=r"(a) : "l"(p));
    return a;
}
__device__ __forceinline__ void cp16(uint32_t dst, const void* src) {
    asm volatile("cp.async.cg.shared.global [%0], [%1], 16;" :: "r"(dst), "l"(src));
}
#define CP_COMMIT() asm volatile("cp.async.commit_group;" ::: "memory")

// m16n8k8 tf32 mma: A frag {(g,t),(g+8,t),(g,t+4),(g+8,t+4)}, B frag {(t,n=g),(t+4,g)}
// C frag {(g,2t),(g,2t+1),(g+8,2t),(g+8,2t+1)}
__device__ __forceinline__ void mma_tf32(float* c, const uint32_t* a, const uint32_t* b) {
    asm volatile("mma.sync.aligned.m16n8k8.row.col.f32.tf32.tf32.f32 "
        "{%0,%1,%2,%3}, {%4,%5,%6,%7}, {%8,%9}, {%0,%1,%2,%3};"
        : "+f"(c[0]), "+f"(c[1]), "+f"(c[2]), "+f"(c[3])
        : "r"(a[0]), "r"(a[1]), "r"(a[2]), "r"(a[3]), "r"(b[0]), "r"(b[1]));
}

// ============================================================
// tf32 mma.sync NT-GEMM: C[M,N] = A[M,K] @ B[N,K]^T + bias
// 128x128x32 CTA tile, 3-stage cp.async, 8 warps (2x4), warp tile 64x32.
// A,B must be pre-rounded to tf32 values.
// ============================================================
#define NCK (DD/32)               // 32 K-chunks
#define GLD 36                    // padded stride (floats)
#define STG_FLOATS (2*128*GLD)    // A+B per stage = 9216 floats
#define GEMM_SMEM (3*STG_FLOATS*4)  // 110,592 bytes

__global__ __launch_bounds__(256, 2) void gemm_nt_mma(
    const float* __restrict__ A, const float* __restrict__ Bm,
    const float* __restrict__ bias, float* __restrict__ C)
{
    extern __shared__ float sm[];
    const uint32_t smb = smem_u32(sm);
    const int tid = threadIdx.x, lane = tid & 31, wid = tid >> 5;
    const int g = lane >> 2, t = lane & 3;
    const int wm = wid >> 2, wn = wid & 3;
    const int brow = blockIdx.y * 128, bcol = blockIdx.x * 128;

    float acc[4][4][4] = {};

    const float* Ag = A + (size_t)brow * DD;
    const float* Bg = Bm + (size_t)bcol * DD;

    auto load_stage = [&](int ck, int s) {
        uint32_t abase = smb + (uint32_t)s * STG_FLOATS * 4;
        uint32_t bbase = abase + 128 * GLD * 4;
        #pragma unroll
        for (int p = 0; p < 4; p++) {
            int idx = tid + p * 256;      // 0..1023
            int r = idx >> 3;             // row 0..127
            int c = (idx & 7) * 4;        // col 0..28
            uint32_t off = (uint32_t)(r * GLD + c) * 4;
            cp16(abase + off, Ag + (size_t)r * DD + ck * 32 + c);
            cp16(bbase + off, Bg + (size_t)r * DD + ck * 32 + c);
        }
        CP_COMMIT();
    };

    load_stage(0, 0);
    load_stage(1, 1);

    for (int ck = 0; ck < NCK; ck++) {
        int s = ck % 3;
        if (ck == NCK - 1) asm volatile("cp.async.wait_group 0;" ::: "memory");
        else               asm volatile("cp.async.wait_group 1;" ::: "memory");
        __syncthreads();
        if (ck + 2 < NCK) load_stage(ck + 2, (ck + 2) % 3);

        const float* As = sm + (size_t)s * STG_FLOATS;
        const float* Bs = As + 128 * GLD;
        #pragma unroll
        for (int kk = 0; kk < 4; kk++) {
            uint32_t af[4][4], bf[4][2];
            #pragma unroll
            for (int mi = 0; mi < 4; mi++) {
                const float* ap = &As[(wm*64 + mi*16 + g) * GLD + kk*8 + t];
                af[mi][0] = __float_as_uint(ap[0]);
                af[mi][1] = __float_as_uint(ap[8*GLD]);
                af[mi][2] = __float_as_uint(ap[4]);
                af[mi][3] = __float_as_uint(ap[8*GLD + 4]);
            }
            #pragma unroll
            for (int ni = 0; ni < 4; ni++) {
                const float* bp = &Bs[(wn*32 + ni*8 + g) * GLD + kk*8 + t];
                bf[ni][0] = __float_as_uint(bp[0]);
                bf[ni][1] = __float_as_uint(bp[4]);
            }
            #pragma unroll
            for (int mi = 0; mi < 4; mi++)
                #pragma unroll
                for (int ni = 0; ni < 4; ni++)
                    mma_tf32(acc[mi][ni], af[mi], bf[ni]);
        }
    }

    #pragma unroll
    for (int mi = 0; mi < 4; mi++) {
        int r0 = brow + wm*64 + mi*16 + g;
        #pragma unroll
        for (int ni = 0; ni < 4; ni++) {
            int col = bcol + wn*32 + ni*8 + 2*t;
            float b0 = __ldg(bias + col), b1 = __ldg(bias + col + 1);
            float2 v0 = make_float2(acc[mi][ni][0] + b0, acc[mi][ni][1] + b1);
            float2 v1 = make_float2(acc[mi][ni][2] + b0, acc[mi][ni][3] + b1);
            *(float2*)(C + (size_t)r0 * DD + col) = v0;
            *(float2*)(C + (size_t)(r0 + 8) * DD + col) = v1;
        }
    }
}

// ============================================================
// round fp32 -> tf32 (rna) elementwise, float4
// ============================================================
__global__ void round_tf32_kernel(const float* __restrict__ in,
                                  float* __restrict__ out, int n4)
{
    int i = blockIdx.x * blockDim.x + threadIdx.x;
    if (i < n4) {
        float4 v = ((const float4*)in)[i];
        v.x = to_tf32(v.x); v.y = to_tf32(v.y);
        v.z = to_tf32(v.z); v.w = to_tf32(v.w);
        ((float4*)out)[i] = v;
    }
}

// ============================================================
// feature map (tf32 mma.sync) + softplus
// Out[bh][s][f] = softplus( sum_d Y[b*S+s][h*64+d] * rf[h][d][f] )
// NN GEMM, K=64.  A tile 128x64 (pad 68), B tile 64x128 (pad 136).
// grid (F/128=2, S/128=32, 64)
// ============================================================
#define FA_LD 68
#define FB_LD 136
#define FEAT_SMEM ((128*FA_LD + 64*FB_LD) * 4)   // 69,632 bytes

__device__ __forceinline__ float softplus_f(float x) {
    return (x > 15.f) ? x : log1pf(expf(x));
}

__global__ __launch_bounds__(256) void feat_mma(
    const float* __restrict__ Yin, const float* __restrict__ rf,
    float* __restrict__ Out)
{
    extern __shared__ float sm[];
    float* As = sm;                 // [128][68]
    float* Bs = sm + 128 * FA_LD;   // [64][136]

    int bh = blockIdx.z;
    int b = bh >> 4, h = bh & 15;
    int brow = blockIdx.y * 128, bcol = blockIdx.x * 128;
    const float* Ab = Yin + ((size_t)(b * SS + brow)) * DD + h * HDIM;
    const float* Bb = rf + (size_t)h * HDIM * FF + bcol;

    int tid = threadIdx.x, lane = tid & 31, wid = tid >> 5;
    int g = lane >> 2, t = lane & 3;
    int wm = wid >> 2, wn = wid & 3;

    // load A 128x64 (8 float4/thread), cvt to tf32
    #pragma unroll
    for (int p = 0; p < 8; p++) {
        int idx = tid + p * 256;        // 0..2047
        int r = idx >> 4, c = (idx & 15) * 4;
        float4 a = *(const float4*)(Ab + (size_t)r * DD + c);
        float* d = &As[r * FA_LD + c];
        d[0] = to_tf32(a.x); d[1] = to_tf32(a.y);
        d[2] = to_tf32(a.z); d[3] = to_tf32(a.w);
    }
    // load B 64x128 (8 float4/thread), cvt
    #pragma unroll
    for (int p = 0; p < 8; p++) {
        int idx = tid + p * 256;
        int r = idx >> 5, c = (idx & 31) * 4;
        float4 v = *(const float4*)(Bb + (size_t)r * FF + c);
        float* d = &Bs[r * FB_LD + c];
        d[0] = to_tf32(v.x); d[1] = to_tf32(v.y);
        d[2] = to_tf32(v.z); d[3] = to_tf32(v.w);
    }
    __syncthreads();

    float acc[4][4][4] = {};
    #pragma unroll
    for (int kk = 0; kk < 8; kk++) {
        uint32_t af[4][4], bf[4][2];
        #pragma unroll
        for (int mi = 0; mi < 4; mi++) {
            const float* ap = &As[(wm*64 + mi*16 + g) * FA_LD + kk*8 + t];
            af[mi][0] = __float_as_uint(ap[0]);
            af[mi][1] = __float_as_uint(ap[8*FA_LD]);
            af[mi][2] = __float_as_uint(ap[4]);
            af[mi][3] = __float_as_uint(ap[8*FA_LD + 4]);
        }
        #pragma unroll
        for (int ni = 0; ni < 4; ni++) {
            const float* bp = &Bs[(kk*8 + t) * FB_LD + wn*32 + ni*8 + g];
            bf[ni][0] = __float_as_uint(bp[0]);
            bf[ni][1] = __float_as_uint(bp[4*FB_LD]);
        }
        #pragma unroll
        for (int mi = 0; mi < 4; mi++)
            #pragma unroll
            for (int ni = 0; ni < 4; ni++)
                mma_tf32(acc[mi][ni], af[mi], bf[ni]);
    }

    #pragma unroll
    for (int mi = 0; mi < 4; mi++) {
        size_t r0 = (size_t)bh * SS + brow + wm*64 + mi*16 + g;
        #pragma unroll
        for (int ni = 0; ni < 4; ni++) {
            int col = bcol + wn*32 + ni*8 + 2*t;
            float2 v0 = make_float2(softplus_f(acc[mi][ni][0]), softplus_f(acc[mi][ni][1]));
            float2 v1 = make_float2(softplus_f(acc[mi][ni][2]), softplus_f(acc[mi][ni][3]));
            *(float2*)(Out + r0 * FF + col) = v0;
            *(float2*)(Out + (r0 + 8) * FF + col) = v1;
        }
    }
}

// ============================================================
// kv partials (fp32)
// ============================================================
__global__ __launch_bounds__(256) void kv_kernel(
    const float* __restrict__ Kp, const float* __restrict__ Vm,
    float* __restrict__ KVp, float* __restrict__ KSp)
{
    int bh = blockIdx.x;
    int kc = blockIdx.y;
    int b = bh >> 4, h = bh & 15;
    const float* Ab = Kp + ((size_t)bh * SS + (size_t)kc * SCH) * FF;
    const float* Vb = Vm + ((size_t)(b * SS + kc * SCH)) * DD + h * HDIM;

    __shared__ float At[32][FF];
    __shared__ float Vt[32][HDIM];
    int tid = threadIdx.x;
    int ty = tid >> 3, tx = tid & 7;
    float acc[8][8] = {};
    float rsum[8] = {};

    for (int s0 = 0; s0 < SCH; s0 += 32) {
        #pragma unroll
        for (int p = 0; p < 8; p++) {
            int idx = tid + p * 256;
            int r = idx >> 6, c = (idx & 63) * 4;
            *(float4*)&At[r][c] = *(const float4*)(Ab + (size_t)(s0 + r) * FF + c);
        }
        #pragma unroll
        for (int p = 0; p < 2; p++) {
            int idx = tid + p * 256;
            int r = idx >> 4, c = (idx & 15) * 4;
            *(float4*)&Vt[r][c] = *(const float4*)(Vb + (size_t)(s0 + r) * DD + c);
        }
        __syncthreads();
        #pragma unroll
        for (int ss = 0; ss < 32; ss++) {
            float ra[8], rb[8];
            *(float4*)&ra[0] = *(const float4*)&At[ss][ty*8];
            *(float4*)&ra[4] = *(const float4*)&At[ss][ty*8+4];
            *(float4*)&rb[0] = *(const float4*)&Vt[ss][tx*8];
            *(float4*)&rb[4] = *(const float4*)&Vt[ss][tx*8+4];
            #pragma unroll
            for (int i = 0; i < 8; i++) {
                rsum[i] += ra[i];
                #pragma unroll
                for (int j = 0; j < 8; j++)
                    acc[i][j] += ra[i] * rb[j];
            }
        }
        __syncthreads();
    }
    float* kvout = KVp + ((size_t)kc * NBH + bh) * (FF * HDIM);
    #pragma unroll
    for (int i = 0; i < 8; i++) {
        float* p = kvout + (size_t)(ty*8 + i) * HDIM + tx*8;
        *(float4*)p       = make_float4(acc[i][0], acc[i][1], acc[i][2], acc[i][3]);
        *(float4*)(p + 4) = make_float4(acc[i][4], acc[i][5], acc[i][6], acc[i][7]);
    }
    if (tx == 0) {
        float* kso = KSp + ((size_t)kc * NBH + bh) * FF;
        #pragma unroll
        for (int i = 0; i < 8; i++) kso[ty*8 + i] = rsum[i];
    }
}

__global__ void reduce_kv(const float* __restrict__ KVp, const float* __restrict__ KSp,
                          float* __restrict__ KV, float* __restrict__ KS)
{
    const int NKV = NBH * FF * HDIM;
    const int NKS = NBH * FF;
    int i = blockIdx.x * blockDim.x + threadIdx.x;
    if (i < NKV) {
        float s = 0.f;
        #pragma unroll
        for (int kc = 0; kc < KSPLIT; kc++) s += KVp[(size_t)kc * NKV + i];
        KV[i] = s;
    }
    if (i < NKS) {
        float s = 0.f;
        #pragma unroll
        for (int kc = 0; kc < KSPLIT; kc++) s += KSp[(size_t)kc * NKS + i];
        KS[i] = s;
    }
}

// ============================================================
// qkv + denom + divide; attn rounded to tf32 at store
// ============================================================
__global__ __launch_bounds__(256) void qkv_kernel(
    const float* __restrict__ Qp, const float* __restrict__ KV,
    const float* __restrict__ KS, float* __restrict__ Attn)
{
    constexpr int BM = 128, BK = 32;
    int bh = blockIdx.y;
    int b = bh >> 4, h = bh & 15;
    int brow = blockIdx.x * BM;
    const float* Ab  = Qp + ((size_t)bh * SS + brow) * FF;
    const float* KVb = KV + (size_t)bh * FF * HDIM;
    const float* KSb = KS + (size_t)bh * FF;

    __shared__ float At[BK][BM];
    __shared__ float Bt[BK][HDIM];
    __shared__ float ks[BK];
    int tid = threadIdx.x;
    int ty = tid >> 3, tx = tid & 7;
    float acc[4][8] = {};
    float dacc[4] = {};

    for (int f0 = 0; f0 < FF; f0 += BK) {
        #pragma unroll
        for (int p = 0; p < 4; p++) {
            int idx = tid + p * 256;
            int r = idx >> 3;
            int c = (idx & 7) * 4;
            float4 a = *(const float4*)(Ab + (size_t)r * FF + f0 + c);
            At[c+0][r] = a.x; At[c+1][r] = a.y; At[c+2][r] = a.z; At[c+3][r] = a.w;
        }
        #pragma unroll
        for (int p = 0; p < 2; p++) {
            int idx = tid + p * 256;
            int r = idx >> 4, c = (idx & 15) * 4;
            *(float4*)&Bt[r][c] = *(const float4*)(KVb + (size_t)(f0 + r) * HDIM + c);
        }
        if (tid < BK) ks[tid] = KSb[f0 + tid];
        __syncthreads();
        #pragma unroll
        for (int ff = 0; ff < BK; ff++) {
            float ra[4], rb[8];
            *(float4*)&ra[0] = *(const float4*)&At[ff][ty*4];
            *(float4*)&rb[0] = *(const float4*)&Bt[ff][tx*8];
            *(float4*)&rb[4] = *(const float4*)&Bt[ff][tx*8+4];
            float kv_s = ks[ff];
            #pragma unroll
            for (int i = 0; i < 4; i++) {
                dacc[i] += ra[i] * kv_s;
                #pragma unroll
                for (int j = 0; j < 8; j++)
                    acc[i][j] += ra[i] * rb[j];
            }
        }
        __syncthreads();
    }
    #pragma unroll
    for (int i = 0; i < 4; i++) {
        float inv = 1.f / (dacc[i] + 1e-8f);
        size_t row = (size_t)(b * SS + brow + ty*4 + i);
        float* p = Attn + row * DD + h * HDIM + tx*8;
        *(float4*)p = make_float4(to_tf32(acc[i][0]*inv), to_tf32(acc[i][1]*inv),
                                  to_tf32(acc[i][2]*inv), to_tf32(acc[i][3]*inv));
        *(float4*)(p+4) = make_float4(to_tf32(acc[i][4]*inv), to_tf32(acc[i][5]*inv),
                                      to_tf32(acc[i][6]*inv), to_tf32(acc[i][7]*inv));
    }
}

// ============================================================
extern "C" void kernel_launch(void* const* d_in, const int* in_sizes, int n_in,
                              void* d_out, int out_size)
{
    const float* x  = (const float*)d_in[0];
    const float* Wq = (const float*)d_in[1];
    const float* bq = (const float*)d_in[2];
    const float* Wk = (const float*)d_in[3];
    const float* bk = (const float*)d_in[4];
    const float* Wv = (const float*)d_in[5];
    const float* bv = (const float*)d_in[6];
    const float* Wo = (const float*)d_in[7];
    const float* bo = (const float*)d_in[8];
    const float* rf = (const float*)d_in[9];
    float* out = (float*)d_out;

    void *pq, *pk, *pv, *pqp, *pkp, *pkvp, *pksp, *pkv, *pks, *pattn;
    void *pxr, *pwq, *pwk, *pwv, *pwo;
    cudaGetSymbolAddress(&pq, g_q);
    cudaGetSymbolAddress(&pk, g_k);
    cudaGetSymbolAddress(&pv, g_v);
    cudaGetSymbolAddress(&pqp, g_qp);
    cudaGetSymbolAddress(&pkp, g_kp);
    cudaGetSymbolAddress(&pkvp, g_kvp);
    cudaGetSymbolAddress(&pksp, g_ksp);
    cudaGetSymbolAddress(&pkv, g_kv);
    cudaGetSymbolAddress(&pks, g_ks);
    cudaGetSymbolAddress(&pattn, g_attn);
    cudaGetSymbolAddress(&pxr, g_xr);
    cudaGetSymbolAddress(&pwq, g_wqr);
    cudaGetSymbolAddress(&pwk, g_wkr);
    cudaGetSymbolAddress(&pwv, g_wvr);
    cudaGetSymbolAddress(&pwo, g_wor);

    cudaFuncSetAttribute(gemm_nt_mma, cudaFuncAttributeMaxDynamicSharedMemorySize, GEMM_SMEM);
    cudaFuncSetAttribute(feat_mma, cudaFuncAttributeMaxDynamicSharedMemorySize, FEAT_SMEM);

    // pre-round inputs to tf32 (rna) so HW truncation in mma is exact
    round_tf32_kernel<<<(MM*DD/4 + 255)/256, 256>>>(x, (float*)pxr, MM*DD/4);
    round_tf32_kernel<<<(DD*DD/4 + 255)/256, 256>>>(Wq, (float*)pwq, DD*DD/4);
    round_tf32_kernel<<<(DD*DD/4 + 255)/256, 256>>>(Wk, (float*)pwk, DD*DD/4);
    round_tf32_kernel<<<(DD*DD/4 + 255)/256, 256>>>(Wv, (float*)pwv, DD*DD/4);
    round_tf32_kernel<<<(DD*DD/4 + 255)/256, 256>>>(Wo, (float*)pwo, DD*DD/4);

    dim3 gProj(DD/128, MM/128);     // (8, 128)
    gemm_nt_mma<<<gProj, 256, GEMM_SMEM>>>((const float*)pxr, (const float*)pwq, bq, (float*)pq);
    gemm_nt_mma<<<gProj, 256, GEMM_SMEM>>>((const float*)pxr, (const float*)pwk, bk, (float*)pk);
    gemm_nt_mma<<<gProj, 256, GEMM_SMEM>>>((const float*)pxr, (const float*)pwv, bv, (float*)pv);

    dim3 gFeat(FF/128, SS/128, NBH); // (2, 32, 64)
    feat_mma<<<gFeat, 256, FEAT_SMEM>>>((const float*)pq, rf, (float*)pqp);
    feat_mma<<<gFeat, 256, FEAT_SMEM>>>((const float*)pk, rf, (float*)pkp);

    dim3 gKV(NBH, KSPLIT);           // (64, 8)
    kv_kernel<<<gKV, 256>>>((const float*)pkp, (const float*)pv,
                            (float*)pkvp, (float*)pksp);

    int nred = NBH * FF * HDIM;
    reduce_kv<<<(nred + 255)/256, 256>>>((const float*)pkvp, (const float*)pksp,
                                         (float*)pkv, (float*)pks);

    dim3 gQKV(SS/128, NBH);          // (32, 64)
    qkv_kernel<<<gQKV, 256>>>((const float*)pqp, (const float*)pkv,
                              (const float*)pks, (float*)pattn);

    gemm_nt_mma<<<gProj, 256, GEMM_SMEM>>>((const float*)pattn, (const float*)pwo, bo, out);
}

// round 11
// speedup vs baseline: 3.4236x; 1.3060x over previous
#include <cuda_runtime.h>
#include <cuda_fp16.h>
#include <cstdint>
#include <cstddef>

// Problem constants (all compile-time)
#define BB 4
#define SS 4096
#define DD 1024
#define HH 16
#define HDIM 64
#define FF 256
#define MM (BB*SS)          // 16384
#define NBH (BB*HH)         // 64
#define KSPLIT 8
#define SCH (SS/KSPLIT)     // 512

// -------- scratch (static device allocations; allowed) --------
__device__ __half g_xh[(size_t)MM*DD];
__device__ __half g_wqh[(size_t)DD*DD];
__device__ __half g_wkh[(size_t)DD*DD];
__device__ __half g_wvh[(size_t)DD*DD];
__device__ __half g_woh[(size_t)DD*DD];
__device__ __half g_rfT[(size_t)HH*FF*HDIM];
__device__ __half g_qh[(size_t)MM*DD];
__device__ __half g_kh[(size_t)MM*DD];
__device__ float  g_v[(size_t)MM*DD];
__device__ float  g_qp[(size_t)NBH*SS*FF];
__device__ float  g_kp[(size_t)NBH*SS*FF];
__device__ float  g_kvp[(size_t)KSPLIT*NBH*FF*HDIM];
__device__ float  g_ksp[(size_t)KSPLIT*NBH*FF];
__device__ float  g_kv[(size_t)NBH*FF*HDIM];
__device__ float  g_ks[(size_t)NBH*FF];
__device__ __half g_attnh[(size_t)MM*DD];

__device__ __forceinline__ uint32_t smem_u32(const void* p) {
    uint32_t a;
    asm("{ .reg .u64 t; cvta.to.shared.u64 t, %1; cvt.u32.u64 %0, t; }" : "=r"(a) : "l"(p));
    return a;
}
__device__ __forceinline__ void cp16(uint32_t dst, const void* src) {
    asm volatile("cp.async.cg.shared.global [%0], [%1], 16;" :: "r"(dst), "l"(src));
}
#define CP_COMMIT() asm volatile("cp.async.commit_group;" ::: "memory")

// m16n8k16 f16 mma, f32 accumulate.
__device__ __forceinline__ void mma_f16(float* c, const uint32_t* a, const uint32_t* b) {
    asm volatile("mma.sync.aligned.m16n8k16.row.col.f32.f16.f16.f32 "
        "{%0,%1,%2,%3}, {%4,%5,%6,%7}, {%8,%9}, {%0,%1,%2,%3};"
        : "+f"(c[0]), "+f"(c[1]), "+f"(c[2]), "+f"(c[3])
        : "r"(a[0]), "r"(a[1]), "r"(a[2]), "r"(a[3]), "r"(b[0]), "r"(b[1]));
}

// ============================================================
// fp16 mma NT-GEMM: C[M,N] = A[M,K] @ B[N,K]^T + bias
// 128x128 tile, K-chunk 64 halves, 3-stage cp.async, 8 warps (2x4).
// HALF_OUT: 1 -> write __half, 0 -> write float.
// ============================================================
#define ALD 72                    // padded half stride
#define HSTG (256*ALD)            // halves per stage (A 128 rows + B 128 rows)
#define NCKH (DD/64)              // 16 chunks
#define GEMM_SMEM (3*HSTG*2)      // 110,592 bytes

template<int HALF_OUT>
__global__ __launch_bounds__(256, 2) void gemm_nt_h(
    const __half* __restrict__ A, const __half* __restrict__ Bm,
    const float* __restrict__ bias, void* __restrict__ Cv)
{
    extern __shared__ __half smh[];
    const uint32_t smb = smem_u32(smh);
    const int tid = threadIdx.x, lane = tid & 31, wid = tid >> 5;
    const int g = lane >> 2, t = lane & 3;
    const int wm = wid >> 2, wn = wid & 3;
    const int brow = blockIdx.y * 128, bcol = blockIdx.x * 128;

    float acc[4][4][4] = {};

    const __half* Ag = A + (size_t)brow * DD;
    const __half* Bg = Bm + (size_t)bcol * DD;

    auto load_stage = [&](int ck, int s) {
        uint32_t abase = smb + (uint32_t)s * HSTG * 2;
        uint32_t bbase = abase + 128 * ALD * 2;
        #pragma unroll
        for (int p = 0; p < 4; p++) {
            int idx = tid + p * 256;       // 0..1023
            int r = idx >> 3, c8 = idx & 7;
            uint32_t off = (uint32_t)(r * ALD + c8 * 8) * 2;
            cp16(abase + off, Ag + (size_t)r * DD + ck * 64 + c8 * 8);
            cp16(bbase + off, Bg + (size_t)r * DD + ck * 64 + c8 * 8);
        }
        CP_COMMIT();
    };

    load_stage(0, 0);
    load_stage(1, 1);

    for (int ck = 0; ck < NCKH; ck++) {
        int s = ck % 3;
        if (ck == NCKH - 1) asm volatile("cp.async.wait_group 0;" ::: "memory");
        else                asm volatile("cp.async.wait_group 1;" ::: "memory");
        __syncthreads();
        if (ck + 2 < NCKH) load_stage(ck + 2, (ck + 2) % 3);

        const __half* As = smh + (size_t)s * HSTG;
        const __half* Bs = As + 128 * ALD;
        #pragma unroll
        for (int kk = 0; kk < 4; kk++) {
            uint32_t af[4][4], bf[4][2];
            #pragma unroll
            for (int mi = 0; mi < 4; mi++) {
                const __half* ap = &As[(wm*64 + mi*16 + g) * ALD + kk*16 + 2*t];
                af[mi][0] = *(const uint32_t*)ap;
                af[mi][1] = *(const uint32_t*)(ap + 8*ALD);
                af[mi][2] = *(const uint32_t*)(ap + 8);
                af[mi][3] = *(const uint32_t*)(ap + 8*ALD + 8);
            }
            #pragma unroll
            for (int ni = 0; ni < 4; ni++) {
                const __half* bp = &Bs[(wn*32 + ni*8 + g) * ALD + kk*16 + 2*t];
                bf[ni][0] = *(const uint32_t*)bp;
                bf[ni][1] = *(const uint32_t*)(bp + 8);
            }
            #pragma unroll
            for (int mi = 0; mi < 4; mi++)
                #pragma unroll
                for (int ni = 0; ni < 4; ni++)
                    mma_f16(acc[mi][ni], af[mi], bf[ni]);
        }
    }

    #pragma unroll
    for (int mi = 0; mi < 4; mi++) {
        int r0 = brow + wm*64 + mi*16 + g;
        #pragma unroll
        for (int ni = 0; ni < 4; ni++) {
            int col = bcol + wn*32 + ni*8 + 2*t;
            float b0 = __ldg(bias + col), b1 = __ldg(bias + col + 1);
            float v00 = acc[mi][ni][0] + b0, v01 = acc[mi][ni][1] + b1;
            float v10 = acc[mi][ni][2] + b0, v11 = acc[mi][ni][3] + b1;
            if (HALF_OUT) {
                __half* C = (__half*)Cv;
                __half2 h0 = __floats2half2_rn(v00, v01);
                __half2 h1 = __floats2half2_rn(v10, v11);
                *(uint32_t*)(C + (size_t)r0 * DD + col) = *(uint32_t*)&h0;
                *(uint32_t*)(C + (size_t)(r0 + 8) * DD + col) = *(uint32_t*)&h1;
            } else {
                float* C = (float*)Cv;
                *(float2*)(C + (size_t)r0 * DD + col) = make_float2(v00, v01);
                *(float2*)(C + (size_t)(r0 + 8) * DD + col) = make_float2(v10, v11);
            }
        }
    }
}

// ============================================================
// conversions
// ============================================================
__global__ void cvt_half_kernel(const float* __restrict__ in,
                                __half* __restrict__ out, int n4)
{
    int i = blockIdx.x * blockDim.x + threadIdx.x;
    if (i < n4) {
        float4 v = ((const float4*)in)[i];
        __half2 h0 = __floats2half2_rn(v.x, v.y);
        __half2 h1 = __floats2half2_rn(v.z, v.w);
        ((uint2*)out)[i] = make_uint2(*(uint32_t*)&h0, *(uint32_t*)&h1);
    }
}

// rf[h][d][f] -> rfT[h][f][d] as half
__global__ void rf_transpose_kernel(const float* __restrict__ rf,
                                    __half* __restrict__ rfT)
{
    int h = blockIdx.x;
    int f = threadIdx.x;       // 256 threads = one f each
    const float* src = rf + (size_t)h * HDIM * FF + f;
    __half* dst = rfT + (size_t)h * FF * HDIM + (size_t)f * HDIM;
    #pragma unroll
    for (int d = 0; d < HDIM; d++)
        dst[d] = __float2half_rn(src[(size_t)d * FF]);
}

// ============================================================
// feature map (fp16 mma) + softplus
// Out[bh][s][f] = softplus( sum_d Yh[b*S+s][h*64+d] * rfT[h][f][d] )
// K=64 single shot (4 k-steps). grid (2, 32, 64), block 256.
// ============================================================
#define FEAT_SMEM (256*ALD*2)   // 36,864 bytes

__device__ __forceinline__ float softplus_f(float x) {
    return (x > 15.f) ? x : log1pf(expf(x));
}

__global__ __launch_bounds__(256) void feat_h(
    const __half* __restrict__ Yh, const __half* __restrict__ rfT,
    float* __restrict__ Out)
{
    extern __shared__ __half smh[];
    const uint32_t smb = smem_u32(smh);
    int bh = blockIdx.z;
    int b = bh >> 4, h = bh & 15;
    int brow = blockIdx.y * 128, bcol = blockIdx.x * 128;
    const __half* Ag = Yh + ((size_t)(b * SS + brow)) * DD + h * HDIM;
    const __half* Bg = rfT + (size_t)h * FF * HDIM + (size_t)bcol * HDIM;

    int tid = threadIdx.x, lane = tid & 31, wid = tid >> 5;
    int g = lane >> 2, t = lane & 3;
    int wm = wid >> 2, wn = wid & 3;

    {
        uint32_t abase = smb;
        uint32_t bbase = smb + 128 * ALD * 2;
        #pragma unroll
        for (int p = 0; p < 4; p++) {
            int idx = tid + p * 256;
            int r = idx >> 3, c8 = idx & 7;
            uint32_t off = (uint32_t)(r * ALD + c8 * 8) * 2;
            cp16(abase + off, Ag + (size_t)r * DD + c8 * 8);
            cp16(bbase + off, Bg + (size_t)r * HDIM + c8 * 8);
        }
        CP_COMMIT();
        asm volatile("cp.async.wait_group 0;" ::: "memory");
        __syncthreads();
    }

    const __half* As = smh;
    const __half* Bs = smh + 128 * ALD;
    float acc[4][4][4] = {};
    #pragma unroll
    for (int kk = 0; kk < 4; kk++) {
        uint32_t af[4][4], bf[4][2];
        #pragma unroll
        for (int mi = 0; mi < 4; mi++) {
            const __half* ap = &As[(wm*64 + mi*16 + g) * ALD + kk*16 + 2*t];
            af[mi][0] = *(const uint32_t*)ap;
            af[mi][1] = *(const uint32_t*)(ap + 8*ALD);
            af[mi][2] = *(const uint32_t*)(ap + 8);
            af[mi][3] = *(const uint32_t*)(ap + 8*ALD + 8);
        }
        #pragma unroll
        for (int ni = 0; ni < 4; ni++) {
            const __half* bp = &Bs[(wn*32 + ni*8 + g) * ALD + kk*16 + 2*t];
            bf[ni][0] = *(const uint32_t*)bp;
            bf[ni][1] = *(const uint32_t*)(bp + 8);
        }
        #pragma unroll
        for (int mi = 0; mi < 4; mi++)
            #pragma unroll
            for (int ni = 0; ni < 4; ni++)
                mma_f16(acc[mi][ni], af[mi], bf[ni]);
    }

    #pragma unroll
    for (int mi = 0; mi < 4; mi++) {
        size_t r0 = (size_t)bh * SS + brow + wm*64 + mi*16 + g;
        #pragma unroll
        for (int ni = 0; ni < 4; ni++) {
            int col = bcol + wn*32 + ni*8 + 2*t;
            float2 v0 = make_float2(softplus_f(acc[mi][ni][0]), softplus_f(acc[mi][ni][1]));
            float2 v1 = make_float2(softplus_f(acc[mi][ni][2]), softplus_f(acc[mi][ni][3]));
            *(float2*)(Out + r0 * FF + col) = v0;
            *(float2*)(Out + (r0 + 8) * FF + col) = v1;
        }
    }
}

// ============================================================
// kv partials (fp32)
// ============================================================
__global__ __launch_bounds__(256) void kv_kernel(
    const float* __restrict__ Kp, const float* __restrict__ Vm,
    float* __restrict__ KVp, float* __restrict__ KSp)
{
    int bh = blockIdx.x;
    int kc = blockIdx.y;
    int b = bh >> 4, h = bh & 15;
    const float* Ab = Kp + ((size_t)bh * SS + (size_t)kc * SCH) * FF;
    const float* Vb = Vm + ((size_t)(b * SS + kc * SCH)) * DD + h * HDIM;

    __shared__ float At[32][FF];
    __shared__ float Vt[32][HDIM];
    int tid = threadIdx.x;
    int ty = tid >> 3, tx = tid & 7;
    float acc[8][8] = {};
    float rsum[8] = {};

    for (int s0 = 0; s0 < SCH; s0 += 32) {
        #pragma unroll
        for (int p = 0; p < 8; p++) {
            int idx = tid + p * 256;
            int r = idx >> 6, c = (idx & 63) * 4;
            *(float4*)&At[r][c] = *(const float4*)(Ab + (size_t)(s0 + r) * FF + c);
        }
        #pragma unroll
        for (int p = 0; p < 2; p++) {
            int idx = tid + p * 256;
            int r = idx >> 4, c = (idx & 15) * 4;
            *(float4*)&Vt[r][c] = *(const float4*)(Vb + (size_t)(s0 + r) * DD + c);
        }
        __syncthreads();
        #pragma unroll
        for (int ss = 0; ss < 32; ss++) {
            float ra[8], rb[8];
            *(float4*)&ra[0] = *(const float4*)&At[ss][ty*8];
            *(float4*)&ra[4] = *(const float4*)&At[ss][ty*8+4];
            *(float4*)&rb[0] = *(const float4*)&Vt[ss][tx*8];
            *(float4*)&rb[4] = *(const float4*)&Vt[ss][tx*8+4];
            #pragma unroll
            for (int i = 0; i < 8; i++) {
                rsum[i] += ra[i];
                #pragma unroll
                for (int j = 0; j < 8; j++)
                    acc[i][j] += ra[i] * rb[j];
            }
        }
        __syncthreads();
    }
    float* kvout = KVp + ((size_t)kc * NBH + bh) * (FF * HDIM);
    #pragma unroll
    for (int i = 0; i < 8; i++) {
        float* p = kvout + (size_t)(ty*8 + i) * HDIM + tx*8;
        *(float4*)p       = make_float4(acc[i][0], acc[i][1], acc[i][2], acc[i][3]);
        *(float4*)(p + 4) = make_float4(acc[i][4], acc[i][5], acc[i][6], acc[i][7]);
    }
    if (tx == 0) {
        float* kso = KSp + ((size_t)kc * NBH + bh) * FF;
        #pragma unroll
        for (int i = 0; i < 8; i++) kso[ty*8 + i] = rsum[i];
    }
}

__global__ void reduce_kv(const float* __restrict__ KVp, const float* __restrict__ KSp,
                          float* __restrict__ KV, float* __restrict__ KS)
{
    const int NKV = NBH * FF * HDIM;
    const int NKS = NBH * FF;
    int i = blockIdx.x * blockDim.x + threadIdx.x;
    if (i < NKV) {
        float s = 0.f;
        #pragma unroll
        for (int kc = 0; kc < KSPLIT; kc++) s += KVp[(size_t)kc * NKV + i];
        KV[i] = s;
    }
    if (i < NKS) {
        float s = 0.f;
        #pragma unroll
        for (int kc = 0; kc < KSPLIT; kc++) s += KSp[(size_t)kc * NKS + i];
        KS[i] = s;
    }
}

// ============================================================
// qkv + denom + divide; writes attn as HALF
// ============================================================
__global__ __launch_bounds__(256) void qkv_kernel(
    const float* __restrict__ Qp, const float* __restrict__ KV,
    const float* __restrict__ KS, __half* __restrict__ Attn)
{
    constexpr int BM = 128, BK = 32;
    int bh = blockIdx.y;
    int b = bh >> 4, h = bh & 15;
    int brow = blockIdx.x * BM;
    const float* Ab  = Qp + ((size_t)bh * SS + brow) * FF;
    const float* KVb = KV + (size_t)bh * FF * HDIM;
    const float* KSb = KS + (size_t)bh * FF;

    __shared__ float At[BK][BM];
    __shared__ float Bt[BK][HDIM];
    __shared__ float ks[BK];
    int tid = threadIdx.x;
    int ty = tid >> 3, tx = tid & 7;
    float acc[4][8] = {};
    float dacc[4] = {};

    for (int f0 = 0; f0 < FF; f0 += BK) {
        #pragma unroll
        for (int p = 0; p < 4; p++) {
            int idx = tid + p * 256;
            int r = idx >> 3;
            int c = (idx & 7) * 4;
            float4 a = *(const float4*)(Ab + (size_t)r * FF + f0 + c);
            At[c+0][r] = a.x; At[c+1][r] = a.y; At[c+2][r] = a.z; At[c+3][r] = a.w;
        }
        #pragma unroll
        for (int p = 0; p < 2; p++) {
            int idx = tid + p * 256;
            int r = idx >> 4, c = (idx & 15) * 4;
            *(float4*)&Bt[r][c] = *(const float4*)(KVb + (size_t)(f0 + r) * HDIM + c);
        }
        if (tid < BK) ks[tid] = KSb[f0 + tid];
        __syncthreads();
        #pragma unroll
        for (int ff = 0; ff < BK; ff++) {
            float ra[4], rb[8];
            *(float4*)&ra[0] = *(const float4*)&At[ff][ty*4];
            *(float4*)&rb[0] = *(const float4*)&Bt[ff][tx*8];
            *(float4*)&rb[4] = *(const float4*)&Bt[ff][tx*8+4];
            float kv_s = ks[ff];
            #pragma unroll
            for (int i = 0; i < 4; i++) {
                dacc[i] += ra[i] * kv_s;
                #pragma unroll
                for (int j = 0; j < 8; j++)
                    acc[i][j] += ra[i] * rb[j];
            }
        }
        __syncthreads();
    }
    #pragma unroll
    for (int i = 0; i < 4; i++) {
        float inv = 1.f / (dacc[i] + 1e-8f);
        size_t row = (size_t)(b * SS + brow + ty*4 + i);
        __half2 p0 = __floats2half2_rn(acc[i][0]*inv, acc[i][1]*inv);
        __half2 p1 = __floats2half2_rn(acc[i][2]*inv, acc[i][3]*inv);
        __half2 p2 = __floats2half2_rn(acc[i][4]*inv, acc[i][5]*inv);
        __half2 p3 = __floats2half2_rn(acc[i][6]*inv, acc[i][7]*inv);
        uint4 u = make_uint4(*(uint32_t*)&p0, *(uint32_t*)&p1,
                             *(uint32_t*)&p2, *(uint32_t*)&p3);
        *(uint4*)(Attn + row * DD + h * HDIM + tx*8) = u;
    }
}

// ============================================================
extern "C" void kernel_launch(void* const* d_in, const int* in_sizes, int n_in,
                              void* d_out, int out_size)
{
    const float* x  = (const float*)d_in[0];
    const float* Wq = (const float*)d_in[1];
    const float* bq = (const float*)d_in[2];
    const float* Wk = (const float*)d_in[3];
    const float* bk = (const float*)d_in[4];
    const float* Wv = (const float*)d_in[5];
    const float* bv = (const float*)d_in[6];
    const float* Wo = (const float*)d_in[7];
    const float* bo = (const float*)d_in[8];
    const float* rf = (const float*)d_in[9];
    float* out = (float*)d_out;

    void *pxh, *pwqh, *pwkh, *pwvh, *pwoh, *prfT;
    void *pqh, *pkh, *pv, *pqp, *pkp, *pkvp, *pksp, *pkv, *pks, *pattnh;
    cudaGetSymbolAddress(&pxh, g_xh);
    cudaGetSymbolAddress(&pwqh, g_wqh);
    cudaGetSymbolAddress(&pwkh, g_wkh);
    cudaGetSymbolAddress(&pwvh, g_wvh);
    cudaGetSymbolAddress(&pwoh, g_woh);
    cudaGetSymbolAddress(&prfT, g_rfT);
    cudaGetSymbolAddress(&pqh, g_qh);
    cudaGetSymbolAddress(&pkh, g_kh);
    cudaGetSymbolAddress(&pv, g_v);
    cudaGetSymbolAddress(&pqp, g_qp);
    cudaGetSymbolAddress(&pkp, g_kp);
    cudaGetSymbolAddress(&pkvp, g_kvp);
    cudaGetSymbolAddress(&pksp, g_ksp);
    cudaGetSymbolAddress(&pkv, g_kv);
    cudaGetSymbolAddress(&pks, g_ks);
    cudaGetSymbolAddress(&pattnh, g_attnh);

    cudaFuncSetAttribute(gemm_nt_h<1>, cudaFuncAttributeMaxDynamicSharedMemorySize, GEMM_SMEM);
    cudaFuncSetAttribute(gemm_nt_h<0>, cudaFuncAttributeMaxDynamicSharedMemorySize, GEMM_SMEM);
    cudaFuncSetAttribute(feat_h, cudaFuncAttributeMaxDynamicSharedMemorySize, FEAT_SMEM);

    // conversions
    cvt_half_kernel<<<(MM*DD/4 + 255)/256, 256>>>(x, (__half*)pxh, MM*DD/4);
    cvt_half_kernel<<<(DD*DD/4 + 255)/256, 256>>>(Wq, (__half*)pwqh, DD*DD/4);
    cvt_half_kernel<<<(DD*DD/4 + 255)/256, 256>>>(Wk, (__half*)pwkh, DD*DD/4);
    cvt_half_kernel<<<(DD*DD/4 + 255)/256, 256>>>(Wv, (__half*)pwvh, DD*DD/4);
    cvt_half_kernel<<<(DD*DD/4 + 255)/256, 256>>>(Wo, (__half*)pwoh, DD*DD/4);
    rf_transpose_kernel<<<HH, FF>>>(rf, (__half*)prfT);

    dim3 gProj(DD/128, MM/128);     // (8, 128)
    gemm_nt_h<1><<<gProj, 256, GEMM_SMEM>>>((const __half*)pxh, (const __half*)pwqh, bq, pqh);
    gemm_nt_h<1><<<gProj, 256, GEMM_SMEM>>>((const __half*)pxh, (const __half*)pwkh, bk, pkh);
    gemm_nt_h<0><<<gProj, 256, GEMM_SMEM>>>((const __half*)pxh, (const __half*)pwvh, bv, pv);

    dim3 gFeat(FF/128, SS/128, NBH); // (2, 32, 64)
    feat_h<<<gFeat, 256, FEAT_SMEM>>>((const __half*)pqh, (const __half*)prfT, (float*)pqp);
    feat_h<<<gFeat, 256, FEAT_SMEM>>>((const __half*)pkh, (const __half*)prfT, (float*)pkp);

    dim3 gKV(NBH, KSPLIT);           // (64, 8)
    kv_kernel<<<gKV, 256>>>((const float*)pkp, (const float*)pv,
                            (float*)pkvp, (float*)pksp);

    int nred = NBH * FF * HDIM;
    reduce_kv<<<(nred + 255)/256, 256>>>((const float*)pkvp, (const float*)pksp,
                                         (float*)pkv, (float*)pks);

    dim3 gQKV(SS/128, NBH);          // (32, 64)
    qkv_kernel<<<gQKV, 256>>>((const float*)pqp, (const float*)pkv,
                              (const float*)pks, (__half*)pattnh);

    gemm_nt_h<0><<<gProj, 256, GEMM_SMEM>>>((const __half*)pattnh, (const __half*)pwoh, bo, out);
}